// round 2
// baseline (speedup 1.0000x reference)
#include <cuda_runtime.h>
#include <math.h>
#include <limits.h>

#define TPB 256

__global__ void rm_score_kernel(const int* __restrict__ cid,
                                const int* __restrict__ cmask,
                                const int* __restrict__ rid,
                                const float* __restrict__ ch,
                                const float* __restrict__ rh,
                                const float* __restrict__ w,
                                float* __restrict__ out,
                                int B, int S, int H)
{
    const int b = blockIdx.x;
    const int t = threadIdx.x;
    const int* cidb = cid   + (size_t)b * S;
    const int* cmb  = cmask + (size_t)b * S;
    const int* ridb = rid   + (size_t)b * S;

    __shared__ int   sm[TPB];
    __shared__ float sf[TPB];
    __shared__ int   s_last;

    // ---- pass 1: start_ind = first index where mask != 0 (0 if none, matching argmax) ----
    int mstart = INT_MAX;
    for (int i = t; i < S; i += TPB)
        if (cmb[i] != 0) mstart = min(mstart, i);
    sm[t] = mstart; __syncthreads();
    for (int o = TPB / 2; o > 0; o >>= 1) {
        if (t < o) sm[t] = min(sm[t], sm[t + o]);
        __syncthreads();
    }
    const int start = (sm[0] == INT_MAX) ? 0 : sm[0];
    __syncthreads();

    // ---- pass 2: first PAD (id==0) at/after start in chosen & rejected; any divergence ----
    int cmin = S, rmin = S, diff = 0;
    for (int i = t; i < S; i += TPB) {
        const int c = cidb[i];
        const int r = ridb[i];
        diff |= (c != r);
        if (i >= start) {
            if (c == 0) cmin = min(cmin, i);
            if (r == 0) rmin = min(rmin, i);
        }
    }
    sm[t] = cmin; __syncthreads();
    for (int o = TPB / 2; o > 0; o >>= 1) { if (t < o) sm[t] = min(sm[t], sm[t + o]); __syncthreads(); }
    cmin = sm[0]; __syncthreads();

    sm[t] = rmin; __syncthreads();
    for (int o = TPB / 2; o > 0; o >>= 1) { if (t < o) sm[t] = min(sm[t], sm[t + o]); __syncthreads(); }
    rmin = sm[0]; __syncthreads();

    sm[t] = diff; __syncthreads();
    for (int o = TPB / 2; o > 0; o >>= 1) { if (t < o) sm[t] = max(sm[t], sm[t + o]); __syncthreads(); }
    diff = sm[0]; __syncthreads();

    if (t == 0) {
        // has_div ? r_ind_div : min(c_ind, S)  (c_ind <= S always)
        const int r_ind = diff ? rmin : cmin;
        int last = min(cmin, r_ind) - 1;
        if (last < 0) last += S;   // JAX negative-index wraparound
        s_last = last;
    }
    __syncthreads();
    const int last = s_last;

    // ---- dot products at row `last` only ----
    const float* crow = ch + ((size_t)b * S + (size_t)last) * (size_t)H;
    const float* rrow = rh + ((size_t)b * S + (size_t)last) * (size_t)H;
    float cs = 0.f, rs = 0.f;
    for (int i = t; i < H; i += TPB) {
        const float wi = w[i];
        cs = fmaf(crow[i], wi, cs);
        rs = fmaf(rrow[i], wi, rs);
    }
    sf[t] = cs; __syncthreads();
    for (int o = TPB / 2; o > 0; o >>= 1) { if (t < o) sf[t] += sf[t + o]; __syncthreads(); }
    if (t == 0) out[1 + b] = sf[0];
    __syncthreads();

    sf[t] = rs; __syncthreads();
    for (int o = TPB / 2; o > 0; o >>= 1) { if (t < o) sf[t] += sf[t + o]; __syncthreads(); }
    if (t == 0) out[1 + B + b] = sf[0];
}

__global__ void rm_loss_kernel(float* __restrict__ out, int B)
{
    const int t = threadIdx.x;
    float acc = 0.f;
    for (int i = t; i < B; i += 32) {
        const float d = out[1 + i] - out[1 + B + i];
        // log_sigmoid(d) = min(d,0) - log1p(exp(-|d|))  (numerically stable)
        const float ls = fminf(d, 0.f) - log1pf(expf(-fabsf(d)));
        acc += -ls;
    }
    #pragma unroll
    for (int o = 16; o > 0; o >>= 1)
        acc += __shfl_down_sync(0xffffffffu, acc, o);
    if (t == 0) out[0] = acc / (float)B;
}

extern "C" void kernel_launch(void* const* d_in, const int* in_sizes, int n_in,
                              void* d_out, int out_size)
{
    const int*   cid   = (const int*)d_in[0];
    const int*   cmask = (const int*)d_in[1];
    const int*   rid   = (const int*)d_in[2];
    const float* ch    = (const float*)d_in[3];
    const float* rh    = (const float*)d_in[4];
    const float* w     = (const float*)d_in[5];
    float* out = (float*)d_out;

    const int B = (out_size - 1) / 2;         // out = [loss, chosen[B], rejected[B]]
    const int S = in_sizes[0] / B;            // chosen_ids is [B,S]
    const int H = in_sizes[5];                // v_head_w is [H]

    rm_score_kernel<<<B, TPB>>>(cid, cmask, rid, ch, rh, w, out, B, S, H);
    rm_loss_kernel<<<1, 32>>>(out, B);
}